// round 14
// baseline (speedup 1.0000x reference)
#include <cuda_runtime.h>
#include <cuda_bf16.h>
#include <cstdint>

#define NODES 40000
#define EDGES 640000
#define DIN   128
#define HC    128
#define OC    64
#define NTILES 4000   // 160 edges per tile (10-warp CTAs, 5 row-groups)

typedef unsigned long long ull;

// single dynamic-shared declaration for the whole TU
extern __shared__ char dynsm[];

// ---------------- device scratch ------------------------------------------
__device__ float g_xm[(size_t)NODES * HC];
__device__ float g_xs[(size_t)NODES * OC];
__device__ float g_denom[(size_t)NODES * 2];
__device__ float g_agg[(size_t)NODES * HC];
__device__ float g_le_fallback[(size_t)EDGES * HC];
// W_edge^T split into bf16 hi/lo: [n][k-pair] padded row stride 68 words
__device__ __align__(16) uint32_t g_Bhi[128 * 68];
__device__ __align__(16) uint32_t g_Blo[128 * 68];

// ---------------- helpers ----------------------------------------------------
__device__ __forceinline__ void red_add_v2(float* p, float a, float b) {
    asm volatile("red.global.add.v2.f32 [%0], {%1,%2};"
                 :: "l"(p), "f"(a), "f"(b) : "memory");
}
__device__ __forceinline__ void red_add_f32(float* p, float v) {
    asm volatile("red.global.add.f32 [%0], %1;" :: "l"(p), "f"(v) : "memory");
}
// m16n8k16 row.col bf16 MMA, f32 accumulate (base-target HMMA)
__device__ __forceinline__ void mma_bf16(float* c, const uint32_t* a, const uint32_t* b) {
    asm volatile("mma.sync.aligned.m16n8k16.row.col.f32.bf16.bf16.f32 "
                 "{%0,%1,%2,%3}, {%4,%5,%6,%7}, {%8,%9}, {%0,%1,%2,%3};"
                 : "+f"(c[0]), "+f"(c[1]), "+f"(c[2]), "+f"(c[3])
                 : "r"(a[0]), "r"(a[1]), "r"(a[2]), "r"(a[3]), "r"(b[0]), "r"(b[1]));
}
__device__ __forceinline__ uint32_t pack_bf16x2_split(float v0, float v1, uint32_t& lo) {
    __nv_bfloat16 h0 = __float2bfloat16_rn(v0);
    __nv_bfloat16 h1 = __float2bfloat16_rn(v1);
    __nv_bfloat16 l0 = __float2bfloat16_rn(v0 - __bfloat162float(h0));
    __nv_bfloat16 l1 = __float2bfloat16_rn(v1 - __bfloat162float(h1));
    lo = (uint32_t)__bfloat16_as_ushort(l0) | ((uint32_t)__bfloat16_as_ushort(l1) << 16);
    return (uint32_t)__bfloat16_as_ushort(h0) | ((uint32_t)__bfloat16_as_ushort(h1) << 16);
}

// ---------------- K0: init --------------------------------------------------
__global__ void init_kernel() {
    int i = blockIdx.x * blockDim.x + threadIdx.x;
    if (i < NODES * HC) g_agg[i] = 0.0f;
    if (i < NODES * 2)  g_denom[i] = 0.0f;
}

// ---------------- prep: W_edge^T -> bf16 hi/lo padded [n][k] images ----------
__global__ void prep_kernel(const float* __restrict__ W_edge) {
    int p = blockIdx.x * 256 + threadIdx.x;   // 8192 = 128 n x 64 k-pairs
    if (p >= 8192) return;
    int n  = p >> 6;
    int kp = p & 63;
    int k  = kp * 2;
    uint32_t lo;
    uint32_t hi = pack_bf16x2_split(W_edge[k * HC + n], W_edge[(k + 1) * HC + n], lo);
    g_Bhi[n * 68 + kp] = hi;
    g_Blo[n * 68 + kp] = lo;
}

// ---------------- K1: node GEMMs (known-good) --------------------------------
__global__ void node_kernel(const float* __restrict__ x,
                            const float* __restrict__ W_msg,
                            const float* __restrict__ b_msg,
                            const float* __restrict__ W_self,
                            const float* __restrict__ b_self) {
    float* smf = (float*)dynsm;
    float* Xs = smf;
    float* Wm = smf + 64 * 128;
    float* Wf = Wm + 128 * 128;
    int tid = threadIdx.x;

    const float4* xg = (const float4*)(x + (size_t)blockIdx.x * 64 * DIN);
#pragma unroll
    for (int i = 0; i < 8; i++)  ((float4*)Xs)[tid + i * 256] = xg[tid + i * 256];
#pragma unroll
    for (int i = 0; i < 16; i++) ((float4*)Wm)[tid + i * 256] = ((const float4*)W_msg)[tid + i * 256];
#pragma unroll
    for (int i = 0; i < 8; i++)  ((float4*)Wf)[tid + i * 256] = ((const float4*)W_self)[tid + i * 256];
    __syncthreads();

    int lane = tid & 31, ty = tid >> 5;
    int lane4 = lane * 4;
    const float* Xr = Xs + ty * 8 * DIN;
    {
        float acc[8][4];
#pragma unroll
        for (int r = 0; r < 8; r++) { acc[r][0] = acc[r][1] = acc[r][2] = acc[r][3] = 0.f; }
#pragma unroll 4
        for (int k = 0; k < 128; k++) {
            float4 bq = *(float4*)(Wm + k * 128 + lane4);
#pragma unroll
            for (int r = 0; r < 8; r++) {
                float av = Xr[r * DIN + k];
                acc[r][0] += av * bq.x; acc[r][1] += av * bq.y;
                acc[r][2] += av * bq.z; acc[r][3] += av * bq.w;
            }
        }
        float4 bm = *(const float4*)(b_msg + lane4);
#pragma unroll
        for (int r = 0; r < 8; r++) {
            int n = blockIdx.x * 64 + ty * 8 + r;
            float4 v; v.x = acc[r][0] + bm.x; v.y = acc[r][1] + bm.y;
            v.z = acc[r][2] + bm.z; v.w = acc[r][3] + bm.w;
            *(float4*)(g_xm + (size_t)n * HC + lane4) = v;
        }
    }
    {
        int lane2 = lane * 2;
        float acc[8][2];
#pragma unroll
        for (int r = 0; r < 8; r++) { acc[r][0] = acc[r][1] = 0.f; }
#pragma unroll 4
        for (int k = 0; k < 128; k++) {
            float2 bq = *(float2*)(Wf + k * 64 + lane2);
#pragma unroll
            for (int r = 0; r < 8; r++) {
                float av = Xr[r * DIN + k];
                acc[r][0] += av * bq.x; acc[r][1] += av * bq.y;
            }
        }
        float2 bs = *(const float2*)(b_self + lane2);
#pragma unroll
        for (int r = 0; r < 8; r++) {
            int n = blockIdx.x * 64 + ty * 8 + r;
            float2 v; v.x = acc[r][0] + bs.x; v.y = acc[r][1] + bs.y;
            *(float2*)(g_xs + (size_t)n * OC + lane2) = v;
        }
    }
}

// ---------------- K2: warp-autonomous HMMA edge GEMM + fused scatter ---------
// EXACT R10 structure (best: 305us edge) with ONE change: 320-thread CTAs
// (10 warps = 5 row-groups x 2 col-groups, 160-edge tiles). 2 CTAs/SM now
// gives 20 warps/SM (vs 16) under a 102-reg cap -> +25% latency hiding at
// identical per-edge traffic and identical 32-row B-reuse.
// warp w: rows [(w>>1)*32,+32), cols [(w&1)*64,+64)  (col half == head)
// smem: 0: bias[128] | 512: att[128] | 1024: B_hi(34816) | 35840: B_lo(34816)
#define SM_BHI   1024
#define SM_BLO   35840
#define SM_TOTAL 70656
#define TPB      320
#define TILE_E   160

__global__ void __launch_bounds__(TPB, 2) edge_kernel(
        const float* __restrict__ edge_attr,
        const float* __restrict__ b_edge,
        const float* __restrict__ att,
        const int*   __restrict__ srcIdx,
        const int*   __restrict__ dstIdx,
        float* __restrict__ le_out) {
    char* sm = dynsm;
    int tid = threadIdx.x;
    int wid = tid >> 5;
    int lane = tid & 31;
    float* b_s   = (float*)(sm);
    float* att_s = (float*)(sm + 512);
    uint32_t* Bh32 = (uint32_t*)(sm + SM_BHI);
    uint32_t* Bl32 = (uint32_t*)(sm + SM_BLO);

    // ---- prologue (once per CTA) ----
    if (tid < 128) { b_s[tid] = b_edge[tid]; att_s[tid] = att[tid]; }
    {
        const uint4* bh = (const uint4*)g_Bhi;
        const uint4* bl = (const uint4*)g_Blo;
        uint4* dh = (uint4*)Bh32;
        uint4* dl = (uint4*)Bl32;
#pragma unroll
        for (int i = 0; i < 7; i++) {
            int idx = tid + i * TPB;
            if (idx < 2176) { dh[idx] = bh[idx]; dl[idx] = bl[idx]; }
        }
    }
    __syncthreads();   // the only block sync

    int rowg = wid >> 1;          // 0..4 -> rows rowg*32..+32
    int colg = wid & 1;           // 0..1 -> cols colg*64..+64  (== head)
    int r   = lane >> 2;          // 0..7
    int tig = lane & 3;           // 0..3
    int r0  = rowg * 32 + r;      // lane covers rows r0, r0+8 (mt=0), r0+16, r0+24 (mt=1)

    for (int t = blockIdx.x; t < NTILES; t += gridDim.x) {
        // A tile base, float2 (k-pair) units: row stride = 64 pairs
        const float2* A = (const float2*)(edge_attr + (size_t)t * TILE_E * DIN);

        float acc[2][8][4];
#pragma unroll
        for (int mt = 0; mt < 2; mt++)
#pragma unroll
            for (int nf = 0; nf < 8; nf++)
#pragma unroll
                for (int q = 0; q < 4; q++) acc[mt][nf][q] = 0.f;

        // prefetch first ks raw A: 8 float2 (2 m-tiles x rows r,r+8 x kw,kw+4)
        float2 raw[2][4];
        {
            int kw = tig;
#pragma unroll
            for (int mt = 0; mt < 2; mt++) {
                int R = r0 + mt * 16;
                raw[mt][0] = A[R * 64 + kw];       raw[mt][1] = A[(R + 8) * 64 + kw];
                raw[mt][2] = A[R * 64 + kw + 4];   raw[mt][3] = A[(R + 8) * 64 + kw + 4];
            }
        }
#pragma unroll
        for (int ks = 0; ks < 8; ks++) {
            int kw = ks * 8 + tig;
            uint32_t ah[2][4], al[2][4];
#pragma unroll
            for (int mt = 0; mt < 2; mt++) {
                ah[mt][0] = pack_bf16x2_split(raw[mt][0].x, raw[mt][0].y, al[mt][0]);
                ah[mt][1] = pack_bf16x2_split(raw[mt][1].x, raw[mt][1].y, al[mt][1]);
                ah[mt][2] = pack_bf16x2_split(raw[mt][2].x, raw[mt][2].y, al[mt][2]);
                ah[mt][3] = pack_bf16x2_split(raw[mt][3].x, raw[mt][3].y, al[mt][3]);
            }
            if (ks < 7) {
                int kn = kw + 8;
#pragma unroll
                for (int mt = 0; mt < 2; mt++) {
                    int R = r0 + mt * 16;
                    raw[mt][0] = A[R * 64 + kn];       raw[mt][1] = A[(R + 8) * 64 + kn];
                    raw[mt][2] = A[R * 64 + kn + 4];   raw[mt][3] = A[(R + 8) * 64 + kn + 4];
                }
            }
#pragma unroll
            for (int nf = 0; nf < 8; nf++) {
                int nb = (colg * 64 + nf * 8 + r) * 68 + kw;
                uint32_t bh[2] = { Bh32[nb], Bh32[nb + 4] };
                uint32_t bl[2] = { Bl32[nb], Bl32[nb + 4] };
#pragma unroll
                for (int mt = 0; mt < 2; mt++) {
                    mma_bf16(acc[mt][nf], ah[mt], bh);
                    mma_bf16(acc[mt][nf], ah[mt], bl);
                    mma_bf16(acc[mt][nf], al[mt], bh);
                }
            }
        }

        // ---- epilogue straight from fragments (per m-tile) ----
#pragma unroll
        for (int mt = 0; mt < 2; mt++) {
            int e0 = t * TILE_E + r0 + mt * 16;
            int e1 = e0 + 8;
            int s0 = srcIdx[e0], s1 = srcIdx[e1];
            int d0 = dstIdx[e0], d1 = dstIdx[e1];

            float dot0 = 0.f, dot1 = 0.f;
#pragma unroll
            for (int nf = 0; nf < 8; nf++) {
                int col = colg * 64 + nf * 8 + tig * 2;
                float2 bb = *(float2*)(b_s + col);
                float2 le0; le0.x = acc[mt][nf][0] + bb.x; le0.y = acc[mt][nf][1] + bb.y;
                float2 le1; le1.x = acc[mt][nf][2] + bb.x; le1.y = acc[mt][nf][3] + bb.y;
                *(float2*)(le_out + (size_t)e0 * HC + col) = le0;
                *(float2*)(le_out + (size_t)e1 * HC + col) = le1;
                float2 xv0 = *(const float2*)(g_xm + (size_t)s0 * HC + col);
                float2 xv1 = *(const float2*)(g_xm + (size_t)s1 * HC + col);
                acc[mt][nf][0] = le0.x + xv0.x; acc[mt][nf][1] = le0.y + xv0.y;
                acc[mt][nf][2] = le1.x + xv1.x; acc[mt][nf][3] = le1.y + xv1.y;
                float2 at = *(float2*)(att_s + col);
                dot0 += acc[mt][nf][0] * at.x + acc[mt][nf][1] * at.y;
                dot1 += acc[mt][nf][2] * at.x + acc[mt][nf][3] * at.y;
            }
            dot0 += __shfl_xor_sync(0xffffffffu, dot0, 1);
            dot0 += __shfl_xor_sync(0xffffffffu, dot0, 2);
            dot1 += __shfl_xor_sync(0xffffffffu, dot1, 1);
            dot1 += __shfl_xor_sync(0xffffffffu, dot1, 2);
            float lr0 = dot0 > 0.f ? dot0 : 0.2f * dot0;
            float lr1 = dot1 > 0.f ? dot1 : 0.2f * dot1;
            float ex0 = __expf(lr0);
            float ex1 = __expf(lr1);
            if (tig == 0) {
                red_add_f32(&g_denom[d0 * 2 + colg], ex0);
                red_add_f32(&g_denom[d1 * 2 + colg], ex1);
            }
#pragma unroll
            for (int nf = 0; nf < 8; nf++) {
                int col = colg * 64 + nf * 8 + tig * 2;
                red_add_v2(g_agg + (size_t)d0 * HC + col, acc[mt][nf][0] * ex0, acc[mt][nf][1] * ex0);
                red_add_v2(g_agg + (size_t)d1 * HC + col, acc[mt][nf][2] * ex1, acc[mt][nf][3] * ex1);
            }
        }
    }
}

// ---------------- K3: finalize ----------------------------------------------
__global__ void finalize_kernel(float* __restrict__ out) {
    int i = blockIdx.x * blockDim.x + threadIdx.x;
    if (i >= NODES * OC) return;
    int n = i >> 6;
    int c = i & 63;
    float d0 = g_denom[n * 2 + 0] + 1e-16f;
    float d1 = g_denom[n * 2 + 1] + 1e-16f;
    float v = 0.5f * (g_agg[(size_t)n * HC + c] / d0 + g_agg[(size_t)n * HC + 64 + c] / d1);
    out[i] = v + g_xs[i];
}

// ---------------- launch ------------------------------------------------------
extern "C" void kernel_launch(void* const* d_in, const int* in_sizes, int n_in,
                              void* d_out, int out_size) {
    const float* x        = (const float*)d_in[0];
    const float* edge_attr= (const float*)d_in[1];
    const float* W_msg    = (const float*)d_in[2];
    const float* b_msg    = (const float*)d_in[3];
    const float* W_edge   = (const float*)d_in[4];
    const float* b_edge   = (const float*)d_in[5];
    const float* W_self   = (const float*)d_in[6];
    const float* b_self   = (const float*)d_in[7];
    const float* att      = (const float*)d_in[8];
    const int*   ei       = (const int*)d_in[9];
    const int* srcI = ei;
    const int* dstI = ei + EDGES;

    float* out = (float*)d_out;
    float* le_out;
    bool le_in_out = (out_size >= NODES * OC + (long long)EDGES * HC);
    if (le_in_out) {
        le_out = out + (size_t)NODES * OC;
    } else {
        void* p = nullptr;
        cudaGetSymbolAddress(&p, g_le_fallback);
        le_out = (float*)p;
    }

    cudaFuncSetAttribute(node_kernel, cudaFuncAttributeMaxDynamicSharedMemorySize, 131072);
    cudaFuncSetAttribute(edge_kernel, cudaFuncAttributeMaxDynamicSharedMemorySize, SM_TOTAL);

    init_kernel<<<(NODES * HC + 255) / 256, 256>>>();
    prep_kernel<<<32, 256>>>(W_edge);
    node_kernel<<<NODES / 64, 256, 131072>>>(x, W_msg, b_msg, W_self, b_self);
    edge_kernel<<<296, TPB, SM_TOTAL>>>(edge_attr, b_edge, att, srcI, dstI, le_out);
    finalize_kernel<<<(NODES * OC + 255) / 256, 256>>>(out);
}

// round 15
// speedup vs baseline: 1.5817x; 1.5817x over previous
#include <cuda_runtime.h>
#include <cuda_bf16.h>
#include <cstdint>

#define NODES 40000
#define EDGES 640000
#define DIN   128
#define HC    128
#define OC    64
#define NTILES 5000   // 128 edges per tile
#define NT_TILES 313  // ceil(40000/128) node tiles

typedef unsigned long long ull;

// single dynamic-shared declaration for the whole TU
extern __shared__ char dynsm[];

// ---------------- device scratch ------------------------------------------
__device__ float g_xm[(size_t)NODES * HC];
__device__ float g_xs[(size_t)NODES * OC];
__device__ float g_denom[(size_t)NODES * 2];
__device__ float g_agg[(size_t)NODES * HC];
__device__ float g_le_fallback[(size_t)EDGES * HC];
// W_edge^T split into bf16 hi/lo: [n][k-pair] padded row stride 68 words
__device__ __align__(16) uint32_t g_Bhi[128 * 68];
__device__ __align__(16) uint32_t g_Blo[128 * 68];
// [W_msg | W_self]^T split bf16 hi/lo: 192 rows x 68 k-pair words
__device__ __align__(16) uint32_t g_Bn_hi[192 * 68];
__device__ __align__(16) uint32_t g_Bn_lo[192 * 68];

// ---------------- helpers ----------------------------------------------------
__device__ __forceinline__ void red_add_v2(float* p, float a, float b) {
    asm volatile("red.global.add.v2.f32 [%0], {%1,%2};"
                 :: "l"(p), "f"(a), "f"(b) : "memory");
}
__device__ __forceinline__ void red_add_f32(float* p, float v) {
    asm volatile("red.global.add.f32 [%0], %1;" :: "l"(p), "f"(v) : "memory");
}
// m16n8k16 row.col bf16 MMA, f32 accumulate (base-target HMMA)
__device__ __forceinline__ void mma_bf16(float* c, const uint32_t* a, const uint32_t* b) {
    asm volatile("mma.sync.aligned.m16n8k16.row.col.f32.bf16.bf16.f32 "
                 "{%0,%1,%2,%3}, {%4,%5,%6,%7}, {%8,%9}, {%0,%1,%2,%3};"
                 : "+f"(c[0]), "+f"(c[1]), "+f"(c[2]), "+f"(c[3])
                 : "r"(a[0]), "r"(a[1]), "r"(a[2]), "r"(a[3]), "r"(b[0]), "r"(b[1]));
}
__device__ __forceinline__ uint32_t pack_bf16x2_split(float v0, float v1, uint32_t& lo) {
    __nv_bfloat16 h0 = __float2bfloat16_rn(v0);
    __nv_bfloat16 h1 = __float2bfloat16_rn(v1);
    __nv_bfloat16 l0 = __float2bfloat16_rn(v0 - __bfloat162float(h0));
    __nv_bfloat16 l1 = __float2bfloat16_rn(v1 - __bfloat162float(h1));
    lo = (uint32_t)__bfloat16_as_ushort(l0) | ((uint32_t)__bfloat16_as_ushort(l1) << 16);
    return (uint32_t)__bfloat16_as_ushort(h0) | ((uint32_t)__bfloat16_as_ushort(h1) << 16);
}

// ---------------- K0: init (vectorized) --------------------------------------
__global__ void init_kernel() {
    int i = blockIdx.x * blockDim.x + threadIdx.x;
    if (i < NODES * HC / 4) ((float4*)g_agg)[i] = make_float4(0.f, 0.f, 0.f, 0.f);
    if (i < NODES * 2 / 4)  ((float4*)g_denom)[i] = make_float4(0.f, 0.f, 0.f, 0.f);
}

// ---------------- prep: W_edge^T -> bf16 hi/lo padded [n][k] images ----------
__global__ void prep_kernel(const float* __restrict__ W_edge) {
    int p = blockIdx.x * 256 + threadIdx.x;   // 8192 = 128 n x 64 k-pairs
    if (p >= 8192) return;
    int n  = p >> 6;
    int kp = p & 63;
    int k  = kp * 2;
    uint32_t lo;
    uint32_t hi = pack_bf16x2_split(W_edge[k * HC + n], W_edge[(k + 1) * HC + n], lo);
    g_Bhi[n * 68 + kp] = hi;
    g_Blo[n * 68 + kp] = lo;
}

// prep for node GEMM weights: rows 0..127 = W_msg cols, 128..191 = W_self cols
__global__ void prep_node_kernel(const float* __restrict__ W_msg,
                                 const float* __restrict__ W_self) {
    int p = blockIdx.x * 256 + threadIdx.x;   // 12288 = 192 n x 64 k-pairs
    if (p >= 192 * 64) return;
    int n  = p >> 6;
    int kp = p & 63;
    int k  = kp * 2;
    float v0, v1;
    if (n < 128) { v0 = W_msg[k * HC + n];        v1 = W_msg[(k + 1) * HC + n]; }
    else         { v0 = W_self[k * OC + (n-128)]; v1 = W_self[(k + 1) * OC + (n-128)]; }
    uint32_t lo;
    uint32_t hi = pack_bf16x2_split(v0, v1, lo);
    g_Bn_hi[n * 68 + kp] = hi;
    g_Bn_lo[n * 68 + kp] = lo;
}

// ---------------- K1: node GEMMs via split-bf16 HMMA --------------------------
// [xm | xs] = x @ [W_msg | W_self] + [b_msg | b_self].  N=192, M=128/tile.
// 384 threads = 12 warps: rowg = wid/3 (4 x 32 rows), colg = wid%3 (3 x 64 cols).
// Tail tile rows clamp to NODES-1 -> duplicate identical writes (benign).
// smem: 0: bias[192] | 1024: Bn_hi (52224) | 53248: Bn_lo (52224) -> 105472
#define NSM_BHI  1024
#define NSM_BLO  53248
#define NSM_TOTAL 105472

__global__ void __launch_bounds__(384, 1) node_kernel(
        const float* __restrict__ x,
        const float* __restrict__ b_msg,
        const float* __restrict__ b_self) {
    char* sm = dynsm;
    int tid = threadIdx.x;
    int wid = tid >> 5;
    int lane = tid & 31;
    float* b_s = (float*)(sm);
    uint32_t* Bh32 = (uint32_t*)(sm + NSM_BHI);
    uint32_t* Bl32 = (uint32_t*)(sm + NSM_BLO);

    if (tid < 128) b_s[tid] = b_msg[tid];
    else if (tid < 192) b_s[tid] = b_self[tid - 128];
    {
        const uint4* bh = (const uint4*)g_Bn_hi;
        const uint4* bl = (const uint4*)g_Bn_lo;
        uint4* dh = (uint4*)Bh32;
        uint4* dl = (uint4*)Bl32;
#pragma unroll
        for (int i = 0; i < 9; i++) {
            int idx = tid + i * 384;
            if (idx < 3264) { dh[idx] = bh[idx]; dl[idx] = bl[idx]; }
        }
    }
    __syncthreads();

    int rowg = wid / 3;           // 0..3
    int colg = wid % 3;           // 0..2
    int r   = lane >> 2;
    int tig = lane & 3;
    int r0  = rowg * 32 + r;

    int t = blockIdx.x;
    long tb = (long)t * 128;

    float acc[2][8][4];
#pragma unroll
    for (int mt = 0; mt < 2; mt++)
#pragma unroll
        for (int nf = 0; nf < 8; nf++)
#pragma unroll
            for (int q = 0; q < 4; q++) acc[mt][nf][q] = 0.f;

    // clamped global rows for this lane's 4 result rows
    int gr[2][2];
#pragma unroll
    for (int mt = 0; mt < 2; mt++) {
        long R0 = tb + r0 + mt * 16;
        long R1 = R0 + 8;
        gr[mt][0] = (int)(R0 < NODES ? R0 : NODES - 1);
        gr[mt][1] = (int)(R1 < NODES ? R1 : NODES - 1);
    }

    float2 raw[2][4];
    {
        int kw = tig;
#pragma unroll
        for (int mt = 0; mt < 2; mt++) {
            const float2* A0 = (const float2*)(x + (size_t)gr[mt][0] * DIN);
            const float2* A1 = (const float2*)(x + (size_t)gr[mt][1] * DIN);
            raw[mt][0] = A0[kw];     raw[mt][1] = A1[kw];
            raw[mt][2] = A0[kw + 4]; raw[mt][3] = A1[kw + 4];
        }
    }
#pragma unroll
    for (int ks = 0; ks < 8; ks++) {
        int kw = ks * 8 + tig;
        uint32_t ah[2][4], al[2][4];
#pragma unroll
        for (int mt = 0; mt < 2; mt++) {
            ah[mt][0] = pack_bf16x2_split(raw[mt][0].x, raw[mt][0].y, al[mt][0]);
            ah[mt][1] = pack_bf16x2_split(raw[mt][1].x, raw[mt][1].y, al[mt][1]);
            ah[mt][2] = pack_bf16x2_split(raw[mt][2].x, raw[mt][2].y, al[mt][2]);
            ah[mt][3] = pack_bf16x2_split(raw[mt][3].x, raw[mt][3].y, al[mt][3]);
        }
        if (ks < 7) {
            int kn = kw + 8;
#pragma unroll
            for (int mt = 0; mt < 2; mt++) {
                const float2* A0 = (const float2*)(x + (size_t)gr[mt][0] * DIN);
                const float2* A1 = (const float2*)(x + (size_t)gr[mt][1] * DIN);
                raw[mt][0] = A0[kn];     raw[mt][1] = A1[kn];
                raw[mt][2] = A0[kn + 4]; raw[mt][3] = A1[kn + 4];
            }
        }
#pragma unroll
        for (int nf = 0; nf < 8; nf++) {
            int nb = (colg * 64 + nf * 8 + r) * 68 + kw;
            uint32_t bh[2] = { Bh32[nb], Bh32[nb + 4] };
            uint32_t bl[2] = { Bl32[nb], Bl32[nb + 4] };
#pragma unroll
            for (int mt = 0; mt < 2; mt++) {
                mma_bf16(acc[mt][nf], ah[mt], bh);
                mma_bf16(acc[mt][nf], ah[mt], bl);
                mma_bf16(acc[mt][nf], al[mt], bh);
            }
        }
    }

    // epilogue: bias add, route cols<128 -> g_xm, cols>=128 -> g_xs
#pragma unroll
    for (int mt = 0; mt < 2; mt++) {
        int n0 = gr[mt][0], n1 = gr[mt][1];
#pragma unroll
        for (int nf = 0; nf < 8; nf++) {
            int gcol = colg * 64 + nf * 8 + tig * 2;
            float2 bb = *(float2*)(b_s + gcol);
            float2 v0; v0.x = acc[mt][nf][0] + bb.x; v0.y = acc[mt][nf][1] + bb.y;
            float2 v1; v1.x = acc[mt][nf][2] + bb.x; v1.y = acc[mt][nf][3] + bb.y;
            if (colg < 2) {
                *(float2*)(g_xm + (size_t)n0 * HC + gcol) = v0;
                *(float2*)(g_xm + (size_t)n1 * HC + gcol) = v1;
            } else {
                int c = gcol - 128;
                *(float2*)(g_xs + (size_t)n0 * OC + c) = v0;
                *(float2*)(g_xs + (size_t)n1 * OC + c) = v1;
            }
        }
    }
}

// ---------------- K2: warp-autonomous HMMA edge GEMM + fused scatter ---------
// EXACT R10 (best: 305us). Persistent CTAs, 2/SM. Tile = 128 edges; warp =
// 32 rows x 64 cols as two stacked m16 tiles sharing B fragments. No
// __syncthreads in the tile loop.
// warp w: rows [(w>>1)*32,+32), cols [(w&1)*64,+64)  (col half == head)
// smem: 0: bias[128] | 512: att[128] | 1024: B_hi(34816) | 35840: B_lo(34816)
#define SM_BHI   1024
#define SM_BLO   35840
#define SM_TOTAL 70656

__global__ void __launch_bounds__(256, 2) edge_kernel(
        const float* __restrict__ edge_attr,
        const float* __restrict__ b_edge,
        const float* __restrict__ att,
        const int*   __restrict__ srcIdx,
        const int*   __restrict__ dstIdx,
        float* __restrict__ le_out) {
    char* sm = dynsm;
    int tid = threadIdx.x;
    int wid = tid >> 5;
    int lane = tid & 31;
    float* b_s   = (float*)(sm);
    float* att_s = (float*)(sm + 512);
    uint32_t* Bh32 = (uint32_t*)(sm + SM_BHI);
    uint32_t* Bl32 = (uint32_t*)(sm + SM_BLO);

    if (tid < 128) { b_s[tid] = b_edge[tid]; att_s[tid] = att[tid]; }
    {
        const uint4* bh = (const uint4*)g_Bhi;
        const uint4* bl = (const uint4*)g_Blo;
        uint4* dh = (uint4*)Bh32;
        uint4* dl = (uint4*)Bl32;
#pragma unroll
        for (int i = 0; i < 9; i++) {
            int idx = tid + i * 256;
            if (idx < 2176) { dh[idx] = bh[idx]; dl[idx] = bl[idx]; }
        }
    }
    __syncthreads();   // the only block sync

    int rowg = wid >> 1;
    int colg = wid & 1;
    int r   = lane >> 2;
    int tig = lane & 3;
    int r0  = rowg * 32 + r;

    for (int t = blockIdx.x; t < NTILES; t += gridDim.x) {
        const float2* A = (const float2*)(edge_attr + (size_t)t * 128 * DIN);

        float acc[2][8][4];
#pragma unroll
        for (int mt = 0; mt < 2; mt++)
#pragma unroll
            for (int nf = 0; nf < 8; nf++)
#pragma unroll
                for (int q = 0; q < 4; q++) acc[mt][nf][q] = 0.f;

        float2 raw[2][4];
        {
            int kw = tig;
#pragma unroll
            for (int mt = 0; mt < 2; mt++) {
                int R = r0 + mt * 16;
                raw[mt][0] = A[R * 64 + kw];       raw[mt][1] = A[(R + 8) * 64 + kw];
                raw[mt][2] = A[R * 64 + kw + 4];   raw[mt][3] = A[(R + 8) * 64 + kw + 4];
            }
        }
#pragma unroll
        for (int ks = 0; ks < 8; ks++) {
            int kw = ks * 8 + tig;
            uint32_t ah[2][4], al[2][4];
#pragma unroll
            for (int mt = 0; mt < 2; mt++) {
                ah[mt][0] = pack_bf16x2_split(raw[mt][0].x, raw[mt][0].y, al[mt][0]);
                ah[mt][1] = pack_bf16x2_split(raw[mt][1].x, raw[mt][1].y, al[mt][1]);
                ah[mt][2] = pack_bf16x2_split(raw[mt][2].x, raw[mt][2].y, al[mt][2]);
                ah[mt][3] = pack_bf16x2_split(raw[mt][3].x, raw[mt][3].y, al[mt][3]);
            }
            if (ks < 7) {
                int kn = kw + 8;
#pragma unroll
                for (int mt = 0; mt < 2; mt++) {
                    int R = r0 + mt * 16;
                    raw[mt][0] = A[R * 64 + kn];       raw[mt][1] = A[(R + 8) * 64 + kn];
                    raw[mt][2] = A[R * 64 + kn + 4];   raw[mt][3] = A[(R + 8) * 64 + kn + 4];
                }
            }
#pragma unroll
            for (int nf = 0; nf < 8; nf++) {
                int nb = (colg * 64 + nf * 8 + r) * 68 + kw;
                uint32_t bh[2] = { Bh32[nb], Bh32[nb + 4] };
                uint32_t bl[2] = { Bl32[nb], Bl32[nb + 4] };
#pragma unroll
                for (int mt = 0; mt < 2; mt++) {
                    mma_bf16(acc[mt][nf], ah[mt], bh);
                    mma_bf16(acc[mt][nf], ah[mt], bl);
                    mma_bf16(acc[mt][nf], al[mt], bh);
                }
            }
        }

#pragma unroll
        for (int mt = 0; mt < 2; mt++) {
            int e0 = t * 128 + r0 + mt * 16;
            int e1 = e0 + 8;
            int s0 = srcIdx[e0], s1 = srcIdx[e1];
            int d0 = dstIdx[e0], d1 = dstIdx[e1];

            float dot0 = 0.f, dot1 = 0.f;
#pragma unroll
            for (int nf = 0; nf < 8; nf++) {
                int col = colg * 64 + nf * 8 + tig * 2;
                float2 bb = *(float2*)(b_s + col);
                float2 le0; le0.x = acc[mt][nf][0] + bb.x; le0.y = acc[mt][nf][1] + bb.y;
                float2 le1; le1.x = acc[mt][nf][2] + bb.x; le1.y = acc[mt][nf][3] + bb.y;
                *(float2*)(le_out + (size_t)e0 * HC + col) = le0;
                *(float2*)(le_out + (size_t)e1 * HC + col) = le1;
                float2 xv0 = *(const float2*)(g_xm + (size_t)s0 * HC + col);
                float2 xv1 = *(const float2*)(g_xm + (size_t)s1 * HC + col);
                acc[mt][nf][0] = le0.x + xv0.x; acc[mt][nf][1] = le0.y + xv0.y;
                acc[mt][nf][2] = le1.x + xv1.x; acc[mt][nf][3] = le1.y + xv1.y;
                float2 at = *(float2*)(att_s + col);
                dot0 += acc[mt][nf][0] * at.x + acc[mt][nf][1] * at.y;
                dot1 += acc[mt][nf][2] * at.x + acc[mt][nf][3] * at.y;
            }
            dot0 += __shfl_xor_sync(0xffffffffu, dot0, 1);
            dot0 += __shfl_xor_sync(0xffffffffu, dot0, 2);
            dot1 += __shfl_xor_sync(0xffffffffu, dot1, 1);
            dot1 += __shfl_xor_sync(0xffffffffu, dot1, 2);
            float lr0 = dot0 > 0.f ? dot0 : 0.2f * dot0;
            float lr1 = dot1 > 0.f ? dot1 : 0.2f * dot1;
            float ex0 = __expf(lr0);
            float ex1 = __expf(lr1);
            if (tig == 0) {
                red_add_f32(&g_denom[d0 * 2 + colg], ex0);
                red_add_f32(&g_denom[d1 * 2 + colg], ex1);
            }
#pragma unroll
            for (int nf = 0; nf < 8; nf++) {
                int col = colg * 64 + nf * 8 + tig * 2;
                red_add_v2(g_agg + (size_t)d0 * HC + col, acc[mt][nf][0] * ex0, acc[mt][nf][1] * ex0);
                red_add_v2(g_agg + (size_t)d1 * HC + col, acc[mt][nf][2] * ex1, acc[mt][nf][3] * ex1);
            }
        }
    }
}

// ---------------- K3: finalize (vectorized) -----------------------------------
__global__ void finalize_kernel(float* __restrict__ out) {
    int i = blockIdx.x * blockDim.x + threadIdx.x;   // 4 cols per thread
    if (i >= NODES * OC / 4) return;
    int n  = i >> 4;
    int c4 = (i & 15) * 4;
    float2 dp = *(float2*)(g_denom + n * 2);
    float i0 = 1.0f / (dp.x + 1e-16f);
    float i1 = 1.0f / (dp.y + 1e-16f);
    float4 a0 = *(float4*)(g_agg + (size_t)n * HC + c4);
    float4 a1 = *(float4*)(g_agg + (size_t)n * HC + 64 + c4);
    float4 xs = *(float4*)(g_xs + (size_t)n * OC + c4);
    float4 v;
    v.x = 0.5f * (a0.x * i0 + a1.x * i1) + xs.x;
    v.y = 0.5f * (a0.y * i0 + a1.y * i1) + xs.y;
    v.z = 0.5f * (a0.z * i0 + a1.z * i1) + xs.z;
    v.w = 0.5f * (a0.w * i0 + a1.w * i1) + xs.w;
    *(float4*)(out + (size_t)n * OC + c4) = v;
}

// ---------------- launch ------------------------------------------------------
extern "C" void kernel_launch(void* const* d_in, const int* in_sizes, int n_in,
                              void* d_out, int out_size) {
    const float* x        = (const float*)d_in[0];
    const float* edge_attr= (const float*)d_in[1];
    const float* W_msg    = (const float*)d_in[2];
    const float* b_msg    = (const float*)d_in[3];
    const float* W_edge   = (const float*)d_in[4];
    const float* b_edge   = (const float*)d_in[5];
    const float* W_self   = (const float*)d_in[6];
    const float* b_self   = (const float*)d_in[7];
    const float* att      = (const float*)d_in[8];
    const int*   ei       = (const int*)d_in[9];
    const int* srcI = ei;
    const int* dstI = ei + EDGES;

    float* out = (float*)d_out;
    float* le_out;
    bool le_in_out = (out_size >= NODES * OC + (long long)EDGES * HC);
    if (le_in_out) {
        le_out = out + (size_t)NODES * OC;
    } else {
        void* p = nullptr;
        cudaGetSymbolAddress(&p, g_le_fallback);
        le_out = (float*)p;
    }

    cudaFuncSetAttribute(node_kernel, cudaFuncAttributeMaxDynamicSharedMemorySize, NSM_TOTAL);
    cudaFuncSetAttribute(edge_kernel, cudaFuncAttributeMaxDynamicSharedMemorySize, SM_TOTAL);

    init_kernel<<<(NODES * HC / 4 + 255) / 256, 256>>>();
    prep_kernel<<<32, 256>>>(W_edge);
    prep_node_kernel<<<48, 256>>>(W_msg, W_self);
    node_kernel<<<NT_TILES, 384, NSM_TOTAL>>>(x, b_msg, b_self);
    edge_kernel<<<296, 256, SM_TOTAL>>>(edge_attr, b_edge, att, srcI, dstI, le_out);
    finalize_kernel<<<(NODES * OC / 4 + 255) / 256, 256>>>(out);
}

// round 16
// speedup vs baseline: 1.6514x; 1.0441x over previous
#include <cuda_runtime.h>
#include <cuda_bf16.h>
#include <cstdint>

#define NODES 40000
#define EDGES 640000
#define DIN   128
#define HC    128
#define OC    64
#define NTILES 5000   // 128 edges per tile
#define NT_TILES 313  // ceil(40000/128) node tiles

typedef unsigned long long ull;

// single dynamic-shared declaration for the whole TU
extern __shared__ char dynsm[];

// ---------------- device scratch ------------------------------------------
__device__ float g_xm[(size_t)NODES * HC];
__device__ float g_xs[(size_t)NODES * OC];
__device__ float g_denom[(size_t)NODES * 2];
__device__ float g_agg[(size_t)NODES * HC];
__device__ float g_le_fallback[(size_t)EDGES * HC];
// W_edge^T split into bf16 hi/lo: [n][k-pair] padded row stride 68 words
__device__ __align__(16) uint32_t g_Bhi[128 * 68];
__device__ __align__(16) uint32_t g_Blo[128 * 68];
// [W_msg | W_self]^T split bf16 hi/lo: 192 rows x 68 k-pair words
__device__ __align__(16) uint32_t g_Bn_hi[192 * 68];
__device__ __align__(16) uint32_t g_Bn_lo[192 * 68];

// ---------------- helpers ----------------------------------------------------
__device__ __forceinline__ void red_add_v2(float* p, float a, float b) {
    asm volatile("red.global.add.v2.f32 [%0], {%1,%2};"
                 :: "l"(p), "f"(a), "f"(b) : "memory");
}
__device__ __forceinline__ void red_add_f32(float* p, float v) {
    asm volatile("red.global.add.f32 [%0], %1;" :: "l"(p), "f"(v) : "memory");
}
// m16n8k16 row.col bf16 MMA, f32 accumulate (base-target HMMA)
__device__ __forceinline__ void mma_bf16(float* c, const uint32_t* a, const uint32_t* b) {
    asm volatile("mma.sync.aligned.m16n8k16.row.col.f32.bf16.bf16.f32 "
                 "{%0,%1,%2,%3}, {%4,%5,%6,%7}, {%8,%9}, {%0,%1,%2,%3};"
                 : "+f"(c[0]), "+f"(c[1]), "+f"(c[2]), "+f"(c[3])
                 : "r"(a[0]), "r"(a[1]), "r"(a[2]), "r"(a[3]), "r"(b[0]), "r"(b[1]));
}
__device__ __forceinline__ uint32_t pack_bf16x2_split(float v0, float v1, uint32_t& lo) {
    __nv_bfloat16 h0 = __float2bfloat16_rn(v0);
    __nv_bfloat16 h1 = __float2bfloat16_rn(v1);
    __nv_bfloat16 l0 = __float2bfloat16_rn(v0 - __bfloat162float(h0));
    __nv_bfloat16 l1 = __float2bfloat16_rn(v1 - __bfloat162float(h1));
    lo = (uint32_t)__bfloat16_as_ushort(l0) | ((uint32_t)__bfloat16_as_ushort(l1) << 16);
    return (uint32_t)__bfloat16_as_ushort(h0) | ((uint32_t)__bfloat16_as_ushort(h1) << 16);
}

// ---------------- K0: init (vectorized) --------------------------------------
__global__ void init_kernel() {
    int i = blockIdx.x * blockDim.x + threadIdx.x;
    if (i < NODES * HC / 4) ((float4*)g_agg)[i] = make_float4(0.f, 0.f, 0.f, 0.f);
    if (i < NODES * 2 / 4)  ((float4*)g_denom)[i] = make_float4(0.f, 0.f, 0.f, 0.f);
}

// ---------------- prep: W_edge^T -> bf16 hi/lo padded [n][k] images ----------
__global__ void prep_kernel(const float* __restrict__ W_edge) {
    int p = blockIdx.x * 256 + threadIdx.x;   // 8192 = 128 n x 64 k-pairs
    if (p >= 8192) return;
    int n  = p >> 6;
    int kp = p & 63;
    int k  = kp * 2;
    uint32_t lo;
    uint32_t hi = pack_bf16x2_split(W_edge[k * HC + n], W_edge[(k + 1) * HC + n], lo);
    g_Bhi[n * 68 + kp] = hi;
    g_Blo[n * 68 + kp] = lo;
}

// prep for node GEMM weights: rows 0..127 = W_msg cols, 128..191 = W_self cols
__global__ void prep_node_kernel(const float* __restrict__ W_msg,
                                 const float* __restrict__ W_self) {
    int p = blockIdx.x * 256 + threadIdx.x;   // 12288 = 192 n x 64 k-pairs
    if (p >= 192 * 64) return;
    int n  = p >> 6;
    int kp = p & 63;
    int k  = kp * 2;
    float v0, v1;
    if (n < 128) { v0 = W_msg[k * HC + n];        v1 = W_msg[(k + 1) * HC + n]; }
    else         { v0 = W_self[k * OC + (n-128)]; v1 = W_self[(k + 1) * OC + (n-128)]; }
    uint32_t lo;
    uint32_t hi = pack_bf16x2_split(v0, v1, lo);
    g_Bn_hi[n * 68 + kp] = hi;
    g_Bn_lo[n * 68 + kp] = lo;
}

// ---------------- K1: node GEMMs via split-bf16 HMMA (R15 known-good) ---------
#define NSM_BHI  1024
#define NSM_BLO  53248
#define NSM_TOTAL 105472

__global__ void __launch_bounds__(384, 1) node_kernel(
        const float* __restrict__ x,
        const float* __restrict__ b_msg,
        const float* __restrict__ b_self) {
    char* sm = dynsm;
    int tid = threadIdx.x;
    int wid = tid >> 5;
    int lane = tid & 31;
    float* b_s = (float*)(sm);
    uint32_t* Bh32 = (uint32_t*)(sm + NSM_BHI);
    uint32_t* Bl32 = (uint32_t*)(sm + NSM_BLO);

    if (tid < 128) b_s[tid] = b_msg[tid];
    else if (tid < 192) b_s[tid] = b_self[tid - 128];
    {
        const uint4* bh = (const uint4*)g_Bn_hi;
        const uint4* bl = (const uint4*)g_Bn_lo;
        uint4* dh = (uint4*)Bh32;
        uint4* dl = (uint4*)Bl32;
#pragma unroll
        for (int i = 0; i < 9; i++) {
            int idx = tid + i * 384;
            if (idx < 3264) { dh[idx] = bh[idx]; dl[idx] = bl[idx]; }
        }
    }
    __syncthreads();

    int rowg = wid / 3;
    int colg = wid % 3;
    int r   = lane >> 2;
    int tig = lane & 3;
    int r0  = rowg * 32 + r;

    int t = blockIdx.x;
    long tb = (long)t * 128;

    float acc[2][8][4];
#pragma unroll
    for (int mt = 0; mt < 2; mt++)
#pragma unroll
        for (int nf = 0; nf < 8; nf++)
#pragma unroll
            for (int q = 0; q < 4; q++) acc[mt][nf][q] = 0.f;

    int gr[2][2];
#pragma unroll
    for (int mt = 0; mt < 2; mt++) {
        long R0 = tb + r0 + mt * 16;
        long R1 = R0 + 8;
        gr[mt][0] = (int)(R0 < NODES ? R0 : NODES - 1);
        gr[mt][1] = (int)(R1 < NODES ? R1 : NODES - 1);
    }

    float2 raw[2][4];
    {
        int kw = tig;
#pragma unroll
        for (int mt = 0; mt < 2; mt++) {
            const float2* A0 = (const float2*)(x + (size_t)gr[mt][0] * DIN);
            const float2* A1 = (const float2*)(x + (size_t)gr[mt][1] * DIN);
            raw[mt][0] = A0[kw];     raw[mt][1] = A1[kw];
            raw[mt][2] = A0[kw + 4]; raw[mt][3] = A1[kw + 4];
        }
    }
#pragma unroll
    for (int ks = 0; ks < 8; ks++) {
        int kw = ks * 8 + tig;
        uint32_t ah[2][4], al[2][4];
#pragma unroll
        for (int mt = 0; mt < 2; mt++) {
            ah[mt][0] = pack_bf16x2_split(raw[mt][0].x, raw[mt][0].y, al[mt][0]);
            ah[mt][1] = pack_bf16x2_split(raw[mt][1].x, raw[mt][1].y, al[mt][1]);
            ah[mt][2] = pack_bf16x2_split(raw[mt][2].x, raw[mt][2].y, al[mt][2]);
            ah[mt][3] = pack_bf16x2_split(raw[mt][3].x, raw[mt][3].y, al[mt][3]);
        }
        if (ks < 7) {
            int kn = kw + 8;
#pragma unroll
            for (int mt = 0; mt < 2; mt++) {
                const float2* A0 = (const float2*)(x + (size_t)gr[mt][0] * DIN);
                const float2* A1 = (const float2*)(x + (size_t)gr[mt][1] * DIN);
                raw[mt][0] = A0[kn];     raw[mt][1] = A1[kn];
                raw[mt][2] = A0[kn + 4]; raw[mt][3] = A1[kn + 4];
            }
        }
#pragma unroll
        for (int nf = 0; nf < 8; nf++) {
            int nb = (colg * 64 + nf * 8 + r) * 68 + kw;
            uint32_t bh[2] = { Bh32[nb], Bh32[nb + 4] };
            uint32_t bl[2] = { Bl32[nb], Bl32[nb + 4] };
#pragma unroll
            for (int mt = 0; mt < 2; mt++) {
                mma_bf16(acc[mt][nf], ah[mt], bh);
                mma_bf16(acc[mt][nf], ah[mt], bl);
                mma_bf16(acc[mt][nf], al[mt], bh);
            }
        }
    }

#pragma unroll
    for (int mt = 0; mt < 2; mt++) {
        int n0 = gr[mt][0], n1 = gr[mt][1];
#pragma unroll
        for (int nf = 0; nf < 8; nf++) {
            int gcol = colg * 64 + nf * 8 + tig * 2;
            float2 bb = *(float2*)(b_s + gcol);
            float2 v0; v0.x = acc[mt][nf][0] + bb.x; v0.y = acc[mt][nf][1] + bb.y;
            float2 v1; v1.x = acc[mt][nf][2] + bb.x; v1.y = acc[mt][nf][3] + bb.y;
            if (colg < 2) {
                *(float2*)(g_xm + (size_t)n0 * HC + gcol) = v0;
                *(float2*)(g_xm + (size_t)n1 * HC + gcol) = v1;
            } else {
                int c = gcol - 128;
                *(float2*)(g_xs + (size_t)n0 * OC + c) = v0;
                *(float2*)(g_xs + (size_t)n1 * OC + c) = v1;
            }
        }
    }
}

// ---------------- K2: HMMA edge GEMM + fused scatter (permuted-k frags) ------
// R10/R15 structure with permuted-k fragment mapping: lane t holds k-pairs
// {2t, 2t+1} (valid: A and B agree on the bijection; accumulator unchanged).
//   A: one LDG.128 per row per ks  (was 2x LDG.64)
//   B: one LDS.64 per (nf, hi/lo)  (was 2x LDS.32); stride-68 rows make the
//      .64 accesses perfectly 2-phase (conflict-free minimum).
// ~160 fewer instructions per warp-tile, identical bytes, identical epilogue.
// smem: 0: bias[128] | 512: att[128] | 1024: B_hi(34816) | 35840: B_lo(34816)
#define SM_BHI   1024
#define SM_BLO   35840
#define SM_TOTAL 70656

__global__ void __launch_bounds__(256, 2) edge_kernel(
        const float* __restrict__ edge_attr,
        const float* __restrict__ b_edge,
        const float* __restrict__ att,
        const int*   __restrict__ srcIdx,
        const int*   __restrict__ dstIdx,
        float* __restrict__ le_out) {
    char* sm = dynsm;
    int tid = threadIdx.x;
    int wid = tid >> 5;
    int lane = tid & 31;
    float* b_s   = (float*)(sm);
    float* att_s = (float*)(sm + 512);
    uint32_t* Bh32 = (uint32_t*)(sm + SM_BHI);
    uint32_t* Bl32 = (uint32_t*)(sm + SM_BLO);

    if (tid < 128) { b_s[tid] = b_edge[tid]; att_s[tid] = att[tid]; }
    {
        const uint4* bh = (const uint4*)g_Bhi;
        const uint4* bl = (const uint4*)g_Blo;
        uint4* dh = (uint4*)Bh32;
        uint4* dl = (uint4*)Bl32;
#pragma unroll
        for (int i = 0; i < 9; i++) {
            int idx = tid + i * 256;
            if (idx < 2176) { dh[idx] = bh[idx]; dl[idx] = bl[idx]; }
        }
    }
    __syncthreads();   // the only block sync

    int rowg = wid >> 1;
    int colg = wid & 1;
    int r   = lane >> 2;
    int tig = lane & 3;
    int r0  = rowg * 32 + r;

    for (int t = blockIdx.x; t < NTILES; t += gridDim.x) {
        // A tile base in float4 units: 32 float4 per 128-float row
        const float4* A4 = (const float4*)(edge_attr + (size_t)t * 128 * DIN);

        float acc[2][8][4];
#pragma unroll
        for (int mt = 0; mt < 2; mt++)
#pragma unroll
            for (int nf = 0; nf < 8; nf++)
#pragma unroll
                for (int q = 0; q < 4; q++) acc[mt][nf][q] = 0.f;

        // raw[mt][0] = row r0+mt*16, raw[mt][1] = row +8 ; float4 = pairs {2t,2t+1}
        float4 raw[2][2];
#pragma unroll
        for (int mt = 0; mt < 2; mt++) {
            int R = r0 + mt * 16;
            raw[mt][0] = A4[R * 32 + tig];
            raw[mt][1] = A4[(R + 8) * 32 + tig];
        }
#pragma unroll
        for (int ks = 0; ks < 8; ks++) {
            // fragment: a0 = row r pair 2t (hi of raw.xy), a1 = row r+8 pair 2t,
            //           a2 = row r pair 2t+1 (raw.zw),     a3 = row r+8 pair 2t+1
            uint32_t ah[2][4], al[2][4];
#pragma unroll
            for (int mt = 0; mt < 2; mt++) {
                ah[mt][0] = pack_bf16x2_split(raw[mt][0].x, raw[mt][0].y, al[mt][0]);
                ah[mt][1] = pack_bf16x2_split(raw[mt][1].x, raw[mt][1].y, al[mt][1]);
                ah[mt][2] = pack_bf16x2_split(raw[mt][0].z, raw[mt][0].w, al[mt][2]);
                ah[mt][3] = pack_bf16x2_split(raw[mt][1].z, raw[mt][1].w, al[mt][3]);
            }
            if (ks < 7) {
                int kn = (ks + 1) * 4 + tig;
#pragma unroll
                for (int mt = 0; mt < 2; mt++) {
                    int R = r0 + mt * 16;
                    raw[mt][0] = A4[R * 32 + kn];
                    raw[mt][1] = A4[(R + 8) * 32 + kn];
                }
            }
#pragma unroll
            for (int nf = 0; nf < 8; nf++) {
                // permuted-k B: pairs {2t, 2t+1} contiguous -> one LDS.64 each
                int nb = (colg * 64 + nf * 8 + r) * 68 + ks * 8 + tig * 2;
                uint2 bhv = *(uint2*)(Bh32 + nb);
                uint2 blv = *(uint2*)(Bl32 + nb);
                uint32_t bh[2] = { bhv.x, bhv.y };
                uint32_t bl[2] = { blv.x, blv.y };
#pragma unroll
                for (int mt = 0; mt < 2; mt++) {
                    mma_bf16(acc[mt][nf], ah[mt], bh);
                    mma_bf16(acc[mt][nf], ah[mt], bl);
                    mma_bf16(acc[mt][nf], al[mt], bh);
                }
            }
        }

#pragma unroll
        for (int mt = 0; mt < 2; mt++) {
            int e0 = t * 128 + r0 + mt * 16;
            int e1 = e0 + 8;
            int s0 = srcIdx[e0], s1 = srcIdx[e1];
            int d0 = dstIdx[e0], d1 = dstIdx[e1];

            float dot0 = 0.f, dot1 = 0.f;
#pragma unroll
            for (int nf = 0; nf < 8; nf++) {
                int col = colg * 64 + nf * 8 + tig * 2;
                float2 bb = *(float2*)(b_s + col);
                float2 le0; le0.x = acc[mt][nf][0] + bb.x; le0.y = acc[mt][nf][1] + bb.y;
                float2 le1; le1.x = acc[mt][nf][2] + bb.x; le1.y = acc[mt][nf][3] + bb.y;
                *(float2*)(le_out + (size_t)e0 * HC + col) = le0;
                *(float2*)(le_out + (size_t)e1 * HC + col) = le1;
                float2 xv0 = *(const float2*)(g_xm + (size_t)s0 * HC + col);
                float2 xv1 = *(const float2*)(g_xm + (size_t)s1 * HC + col);
                acc[mt][nf][0] = le0.x + xv0.x; acc[mt][nf][1] = le0.y + xv0.y;
                acc[mt][nf][2] = le1.x + xv1.x; acc[mt][nf][3] = le1.y + xv1.y;
                float2 at = *(float2*)(att_s + col);
                dot0 += acc[mt][nf][0] * at.x + acc[mt][nf][1] * at.y;
                dot1 += acc[mt][nf][2] * at.x + acc[mt][nf][3] * at.y;
            }
            dot0 += __shfl_xor_sync(0xffffffffu, dot0, 1);
            dot0 += __shfl_xor_sync(0xffffffffu, dot0, 2);
            dot1 += __shfl_xor_sync(0xffffffffu, dot1, 1);
            dot1 += __shfl_xor_sync(0xffffffffu, dot1, 2);
            float lr0 = dot0 > 0.f ? dot0 : 0.2f * dot0;
            float lr1 = dot1 > 0.f ? dot1 : 0.2f * dot1;
            float ex0 = __expf(lr0);
            float ex1 = __expf(lr1);
            if (tig == 0) {
                red_add_f32(&g_denom[d0 * 2 + colg], ex0);
                red_add_f32(&g_denom[d1 * 2 + colg], ex1);
            }
#pragma unroll
            for (int nf = 0; nf < 8; nf++) {
                int col = colg * 64 + nf * 8 + tig * 2;
                red_add_v2(g_agg + (size_t)d0 * HC + col, acc[mt][nf][0] * ex0, acc[mt][nf][1] * ex0);
                red_add_v2(g_agg + (size_t)d1 * HC + col, acc[mt][nf][2] * ex1, acc[mt][nf][3] * ex1);
            }
        }
    }
}

// ---------------- K3: finalize (vectorized) -----------------------------------
__global__ void finalize_kernel(float* __restrict__ out) {
    int i = blockIdx.x * blockDim.x + threadIdx.x;   // 4 cols per thread
    if (i >= NODES * OC / 4) return;
    int n  = i >> 4;
    int c4 = (i & 15) * 4;
    float2 dp = *(float2*)(g_denom + n * 2);
    float i0 = 1.0f / (dp.x + 1e-16f);
    float i1 = 1.0f / (dp.y + 1e-16f);
    float4 a0 = *(float4*)(g_agg + (size_t)n * HC + c4);
    float4 a1 = *(float4*)(g_agg + (size_t)n * HC + 64 + c4);
    float4 xs = *(float4*)(g_xs + (size_t)n * OC + c4);
    float4 v;
    v.x = 0.5f * (a0.x * i0 + a1.x * i1) + xs.x;
    v.y = 0.5f * (a0.y * i0 + a1.y * i1) + xs.y;
    v.z = 0.5f * (a0.z * i0 + a1.z * i1) + xs.z;
    v.w = 0.5f * (a0.w * i0 + a1.w * i1) + xs.w;
    *(float4*)(out + (size_t)n * OC + c4) = v;
}

// ---------------- launch ------------------------------------------------------
extern "C" void kernel_launch(void* const* d_in, const int* in_sizes, int n_in,
                              void* d_out, int out_size) {
    const float* x        = (const float*)d_in[0];
    const float* edge_attr= (const float*)d_in[1];
    const float* W_msg    = (const float*)d_in[2];
    const float* b_msg    = (const float*)d_in[3];
    const float* W_edge   = (const float*)d_in[4];
    const float* b_edge   = (const float*)d_in[5];
    const float* W_self   = (const float*)d_in[6];
    const float* b_self   = (const float*)d_in[7];
    const float* att      = (const float*)d_in[8];
    const int*   ei       = (const int*)d_in[9];
    const int* srcI = ei;
    const int* dstI = ei + EDGES;

    float* out = (float*)d_out;
    float* le_out;
    bool le_in_out = (out_size >= NODES * OC + (long long)EDGES * HC);
    if (le_in_out) {
        le_out = out + (size_t)NODES * OC;
    } else {
        void* p = nullptr;
        cudaGetSymbolAddress(&p, g_le_fallback);
        le_out = (float*)p;
    }

    cudaFuncSetAttribute(node_kernel, cudaFuncAttributeMaxDynamicSharedMemorySize, NSM_TOTAL);
    cudaFuncSetAttribute(edge_kernel, cudaFuncAttributeMaxDynamicSharedMemorySize, SM_TOTAL);

    init_kernel<<<(NODES * HC / 4 + 255) / 256, 256>>>();
    prep_kernel<<<32, 256>>>(W_edge);
    prep_node_kernel<<<48, 256>>>(W_msg, W_self);
    node_kernel<<<NT_TILES, 384, NSM_TOTAL>>>(x, b_msg, b_self);
    edge_kernel<<<296, 256, SM_TOTAL>>>(edge_attr, b_edge, att, srcI, dstI, le_out);
    finalize_kernel<<<(NODES * OC / 4 + 255) / 256, 256>>>(out);
}

// round 17
// speedup vs baseline: 1.6857x; 1.0208x over previous
#include <cuda_runtime.h>
#include <cuda_bf16.h>
#include <cstdint>

#define NODES 40000
#define EDGES 640000
#define DIN   128
#define HC    128
#define OC    64
#define NTILES 5000   // 128 edges per tile
#define NT_TILES 313  // ceil(40000/128) node tiles

typedef unsigned long long ull;

// single dynamic-shared declaration for the whole TU
extern __shared__ char dynsm[];

// ---------------- device scratch ------------------------------------------
__device__ float g_xm[(size_t)NODES * HC];
__device__ float g_xs[(size_t)NODES * OC];
__device__ float g_denom[(size_t)NODES * 2];
__device__ float g_agg[(size_t)NODES * HC];
__device__ float g_le_fallback[(size_t)EDGES * HC];
// W_edge^T split into bf16 hi/lo: [n][k-pair] padded row stride 68 words
__device__ __align__(16) uint32_t g_Bhi[128 * 68];
__device__ __align__(16) uint32_t g_Blo[128 * 68];
// [W_msg | W_self]^T split bf16 hi/lo: 192 rows x 68 k-pair words
__device__ __align__(16) uint32_t g_Bn_hi[192 * 68];
__device__ __align__(16) uint32_t g_Bn_lo[192 * 68];

// ---------------- helpers ----------------------------------------------------
__device__ __forceinline__ void red_add_v2(float* p, float a, float b) {
    asm volatile("red.global.add.v2.f32 [%0], {%1,%2};"
                 :: "l"(p), "f"(a), "f"(b) : "memory");
}
__device__ __forceinline__ void red_add_f32(float* p, float v) {
    asm volatile("red.global.add.f32 [%0], %1;" :: "l"(p), "f"(v) : "memory");
}
// m16n8k16 row.col bf16 MMA, f32 accumulate (base-target HMMA)
__device__ __forceinline__ void mma_bf16(float* c, const uint32_t* a, const uint32_t* b) {
    asm volatile("mma.sync.aligned.m16n8k16.row.col.f32.bf16.bf16.f32 "
                 "{%0,%1,%2,%3}, {%4,%5,%6,%7}, {%8,%9}, {%0,%1,%2,%3};"
                 : "+f"(c[0]), "+f"(c[1]), "+f"(c[2]), "+f"(c[3])
                 : "r"(a[0]), "r"(a[1]), "r"(a[2]), "r"(a[3]), "r"(b[0]), "r"(b[1]));
}
__device__ __forceinline__ uint32_t pack_bf16x2_split(float v0, float v1, uint32_t& lo) {
    __nv_bfloat16 h0 = __float2bfloat16_rn(v0);
    __nv_bfloat16 h1 = __float2bfloat16_rn(v1);
    __nv_bfloat16 l0 = __float2bfloat16_rn(v0 - __bfloat162float(h0));
    __nv_bfloat16 l1 = __float2bfloat16_rn(v1 - __bfloat162float(h1));
    lo = (uint32_t)__bfloat16_as_ushort(l0) | ((uint32_t)__bfloat16_as_ushort(l1) << 16);
    return (uint32_t)__bfloat16_as_ushort(h0) | ((uint32_t)__bfloat16_as_ushort(h1) << 16);
}

// ---------------- K0: fused setup: zero accumulators + both weight preps -----
__global__ void setup_kernel(const float* __restrict__ W_edge,
                             const float* __restrict__ W_msg,
                             const float* __restrict__ W_self) {
    int i = blockIdx.x * blockDim.x + threadIdx.x;
    if (i < NODES * HC / 4) ((float4*)g_agg)[i] = make_float4(0.f, 0.f, 0.f, 0.f);
    if (i < NODES * 2 / 4)  ((float4*)g_denom)[i] = make_float4(0.f, 0.f, 0.f, 0.f);
    if (i < 8192) {            // W_edge^T -> hi/lo image
        int n  = i >> 6;
        int kp = i & 63;
        int k  = kp * 2;
        uint32_t lo;
        uint32_t hi = pack_bf16x2_split(W_edge[k * HC + n], W_edge[(k + 1) * HC + n], lo);
        g_Bhi[n * 68 + kp] = hi;
        g_Blo[n * 68 + kp] = lo;
    }
    if (i < 192 * 64) {        // [W_msg|W_self]^T -> hi/lo image
        int n  = i >> 6;
        int kp = i & 63;
        int k  = kp * 2;
        float v0, v1;
        if (n < 128) { v0 = W_msg[k * HC + n];        v1 = W_msg[(k + 1) * HC + n]; }
        else         { v0 = W_self[k * OC + (n-128)]; v1 = W_self[(k + 1) * OC + (n-128)]; }
        uint32_t lo;
        uint32_t hi = pack_bf16x2_split(v0, v1, lo);
        g_Bn_hi[n * 68 + kp] = hi;
        g_Bn_lo[n * 68 + kp] = lo;
    }
}

// ---------------- K1: node GEMMs via split-bf16 HMMA (permuted-k frags) ------
#define NSM_BHI  1024
#define NSM_BLO  53248
#define NSM_TOTAL 105472

__global__ void __launch_bounds__(384, 1) node_kernel(
        const float* __restrict__ x,
        const float* __restrict__ b_msg,
        const float* __restrict__ b_self) {
    char* sm = dynsm;
    int tid = threadIdx.x;
    int wid = tid >> 5;
    int lane = tid & 31;
    float* b_s = (float*)(sm);
    uint32_t* Bh32 = (uint32_t*)(sm + NSM_BHI);
    uint32_t* Bl32 = (uint32_t*)(sm + NSM_BLO);

    if (tid < 128) b_s[tid] = b_msg[tid];
    else if (tid < 192) b_s[tid] = b_self[tid - 128];
    {
        const uint4* bh = (const uint4*)g_Bn_hi;
        const uint4* bl = (const uint4*)g_Bn_lo;
        uint4* dh = (uint4*)Bh32;
        uint4* dl = (uint4*)Bl32;
#pragma unroll
        for (int i = 0; i < 9; i++) {
            int idx = tid + i * 384;
            if (idx < 3264) { dh[idx] = bh[idx]; dl[idx] = bl[idx]; }
        }
    }
    __syncthreads();

    int rowg = wid / 3;
    int colg = wid % 3;
    int r   = lane >> 2;
    int tig = lane & 3;
    int r0  = rowg * 32 + r;

    int t = blockIdx.x;
    long tb = (long)t * 128;

    float acc[2][8][4];
#pragma unroll
    for (int mt = 0; mt < 2; mt++)
#pragma unroll
        for (int nf = 0; nf < 8; nf++)
#pragma unroll
            for (int q = 0; q < 4; q++) acc[mt][nf][q] = 0.f;

    int gr[2][2];
#pragma unroll
    for (int mt = 0; mt < 2; mt++) {
        long R0 = tb + r0 + mt * 16;
        long R1 = R0 + 8;
        gr[mt][0] = (int)(R0 < NODES ? R0 : NODES - 1);
        gr[mt][1] = (int)(R1 < NODES ? R1 : NODES - 1);
    }

    // permuted-k: lane t holds k-pairs {2t, 2t+1} -> float4 loads
    float4 raw[2][2];
#pragma unroll
    for (int mt = 0; mt < 2; mt++) {
        raw[mt][0] = *(const float4*)(x + (size_t)gr[mt][0] * DIN + tig * 4);
        raw[mt][1] = *(const float4*)(x + (size_t)gr[mt][1] * DIN + tig * 4);
    }
#pragma unroll
    for (int ks = 0; ks < 8; ks++) {
        uint32_t ah[2][4], al[2][4];
#pragma unroll
        for (int mt = 0; mt < 2; mt++) {
            ah[mt][0] = pack_bf16x2_split(raw[mt][0].x, raw[mt][0].y, al[mt][0]);
            ah[mt][1] = pack_bf16x2_split(raw[mt][1].x, raw[mt][1].y, al[mt][1]);
            ah[mt][2] = pack_bf16x2_split(raw[mt][0].z, raw[mt][0].w, al[mt][2]);
            ah[mt][3] = pack_bf16x2_split(raw[mt][1].z, raw[mt][1].w, al[mt][3]);
        }
        if (ks < 7) {
            int kn = ((ks + 1) * 4 + tig) * 4;
#pragma unroll
            for (int mt = 0; mt < 2; mt++) {
                raw[mt][0] = *(const float4*)(x + (size_t)gr[mt][0] * DIN + kn);
                raw[mt][1] = *(const float4*)(x + (size_t)gr[mt][1] * DIN + kn);
            }
        }
#pragma unroll
        for (int nf = 0; nf < 8; nf++) {
            int nb = (colg * 64 + nf * 8 + r) * 68 + ks * 8 + tig * 2;
            uint2 bhv = *(uint2*)(Bh32 + nb);
            uint2 blv = *(uint2*)(Bl32 + nb);
            uint32_t bh[2] = { bhv.x, bhv.y };
            uint32_t bl[2] = { blv.x, blv.y };
#pragma unroll
            for (int mt = 0; mt < 2; mt++) {
                mma_bf16(acc[mt][nf], ah[mt], bh);
                mma_bf16(acc[mt][nf], ah[mt], bl);
                mma_bf16(acc[mt][nf], al[mt], bh);
            }
        }
    }

#pragma unroll
    for (int mt = 0; mt < 2; mt++) {
        int n0 = gr[mt][0], n1 = gr[mt][1];
#pragma unroll
        for (int nf = 0; nf < 8; nf++) {
            int gcol = colg * 64 + nf * 8 + tig * 2;
            float2 bb = *(float2*)(b_s + gcol);
            float2 v0; v0.x = acc[mt][nf][0] + bb.x; v0.y = acc[mt][nf][1] + bb.y;
            float2 v1; v1.x = acc[mt][nf][2] + bb.x; v1.y = acc[mt][nf][3] + bb.y;
            if (colg < 2) {
                *(float2*)(g_xm + (size_t)n0 * HC + gcol) = v0;
                *(float2*)(g_xm + (size_t)n1 * HC + gcol) = v1;
            } else {
                int c = gcol - 128;
                *(float2*)(g_xs + (size_t)n0 * OC + c) = v0;
                *(float2*)(g_xs + (size_t)n1 * OC + c) = v1;
            }
        }
    }
}

// ---------------- K2: HMMA edge GEMM + fused scatter (R16 best, unchanged) ---
#define SM_BHI   1024
#define SM_BLO   35840
#define SM_TOTAL 70656

__global__ void __launch_bounds__(256, 2) edge_kernel(
        const float* __restrict__ edge_attr,
        const float* __restrict__ b_edge,
        const float* __restrict__ att,
        const int*   __restrict__ srcIdx,
        const int*   __restrict__ dstIdx,
        float* __restrict__ le_out) {
    char* sm = dynsm;
    int tid = threadIdx.x;
    int wid = tid >> 5;
    int lane = tid & 31;
    float* b_s   = (float*)(sm);
    float* att_s = (float*)(sm + 512);
    uint32_t* Bh32 = (uint32_t*)(sm + SM_BHI);
    uint32_t* Bl32 = (uint32_t*)(sm + SM_BLO);

    if (tid < 128) { b_s[tid] = b_edge[tid]; att_s[tid] = att[tid]; }
    {
        const uint4* bh = (const uint4*)g_Bhi;
        const uint4* bl = (const uint4*)g_Blo;
        uint4* dh = (uint4*)Bh32;
        uint4* dl = (uint4*)Bl32;
#pragma unroll
        for (int i = 0; i < 9; i++) {
            int idx = tid + i * 256;
            if (idx < 2176) { dh[idx] = bh[idx]; dl[idx] = bl[idx]; }
        }
    }
    __syncthreads();   // the only block sync

    int rowg = wid >> 1;
    int colg = wid & 1;
    int r   = lane >> 2;
    int tig = lane & 3;
    int r0  = rowg * 32 + r;

    for (int t = blockIdx.x; t < NTILES; t += gridDim.x) {
        const float4* A4 = (const float4*)(edge_attr + (size_t)t * 128 * DIN);

        float acc[2][8][4];
#pragma unroll
        for (int mt = 0; mt < 2; mt++)
#pragma unroll
            for (int nf = 0; nf < 8; nf++)
#pragma unroll
                for (int q = 0; q < 4; q++) acc[mt][nf][q] = 0.f;

        float4 raw[2][2];
#pragma unroll
        for (int mt = 0; mt < 2; mt++) {
            int R = r0 + mt * 16;
            raw[mt][0] = A4[R * 32 + tig];
            raw[mt][1] = A4[(R + 8) * 32 + tig];
        }
#pragma unroll
        for (int ks = 0; ks < 8; ks++) {
            uint32_t ah[2][4], al[2][4];
#pragma unroll
            for (int mt = 0; mt < 2; mt++) {
                ah[mt][0] = pack_bf16x2_split(raw[mt][0].x, raw[mt][0].y, al[mt][0]);
                ah[mt][1] = pack_bf16x2_split(raw[mt][1].x, raw[mt][1].y, al[mt][1]);
                ah[mt][2] = pack_bf16x2_split(raw[mt][0].z, raw[mt][0].w, al[mt][2]);
                ah[mt][3] = pack_bf16x2_split(raw[mt][1].z, raw[mt][1].w, al[mt][3]);
            }
            if (ks < 7) {
                int kn = (ks + 1) * 4 + tig;
#pragma unroll
                for (int mt = 0; mt < 2; mt++) {
                    int R = r0 + mt * 16;
                    raw[mt][0] = A4[R * 32 + kn];
                    raw[mt][1] = A4[(R + 8) * 32 + kn];
                }
            }
#pragma unroll
            for (int nf = 0; nf < 8; nf++) {
                int nb = (colg * 64 + nf * 8 + r) * 68 + ks * 8 + tig * 2;
                uint2 bhv = *(uint2*)(Bh32 + nb);
                uint2 blv = *(uint2*)(Bl32 + nb);
                uint32_t bh[2] = { bhv.x, bhv.y };
                uint32_t bl[2] = { blv.x, blv.y };
#pragma unroll
                for (int mt = 0; mt < 2; mt++) {
                    mma_bf16(acc[mt][nf], ah[mt], bh);
                    mma_bf16(acc[mt][nf], ah[mt], bl);
                    mma_bf16(acc[mt][nf], al[mt], bh);
                }
            }
        }

#pragma unroll
        for (int mt = 0; mt < 2; mt++) {
            int e0 = t * 128 + r0 + mt * 16;
            int e1 = e0 + 8;
            int s0 = srcIdx[e0], s1 = srcIdx[e1];
            int d0 = dstIdx[e0], d1 = dstIdx[e1];

            float dot0 = 0.f, dot1 = 0.f;
#pragma unroll
            for (int nf = 0; nf < 8; nf++) {
                int col = colg * 64 + nf * 8 + tig * 2;
                float2 bb = *(float2*)(b_s + col);
                float2 le0; le0.x = acc[mt][nf][0] + bb.x; le0.y = acc[mt][nf][1] + bb.y;
                float2 le1; le1.x = acc[mt][nf][2] + bb.x; le1.y = acc[mt][nf][3] + bb.y;
                *(float2*)(le_out + (size_t)e0 * HC + col) = le0;
                *(float2*)(le_out + (size_t)e1 * HC + col) = le1;
                float2 xv0 = *(const float2*)(g_xm + (size_t)s0 * HC + col);
                float2 xv1 = *(const float2*)(g_xm + (size_t)s1 * HC + col);
                acc[mt][nf][0] = le0.x + xv0.x; acc[mt][nf][1] = le0.y + xv0.y;
                acc[mt][nf][2] = le1.x + xv1.x; acc[mt][nf][3] = le1.y + xv1.y;
                float2 at = *(float2*)(att_s + col);
                dot0 += acc[mt][nf][0] * at.x + acc[mt][nf][1] * at.y;
                dot1 += acc[mt][nf][2] * at.x + acc[mt][nf][3] * at.y;
            }
            dot0 += __shfl_xor_sync(0xffffffffu, dot0, 1);
            dot0 += __shfl_xor_sync(0xffffffffu, dot0, 2);
            dot1 += __shfl_xor_sync(0xffffffffu, dot1, 1);
            dot1 += __shfl_xor_sync(0xffffffffu, dot1, 2);
            float lr0 = dot0 > 0.f ? dot0 : 0.2f * dot0;
            float lr1 = dot1 > 0.f ? dot1 : 0.2f * dot1;
            float ex0 = __expf(lr0);
            float ex1 = __expf(lr1);
            if (tig == 0) {
                red_add_f32(&g_denom[d0 * 2 + colg], ex0);
                red_add_f32(&g_denom[d1 * 2 + colg], ex1);
            }
#pragma unroll
            for (int nf = 0; nf < 8; nf++) {
                int col = colg * 64 + nf * 8 + tig * 2;
                red_add_v2(g_agg + (size_t)d0 * HC + col, acc[mt][nf][0] * ex0, acc[mt][nf][1] * ex0);
                red_add_v2(g_agg + (size_t)d1 * HC + col, acc[mt][nf][2] * ex1, acc[mt][nf][3] * ex1);
            }
        }
    }
}

// ---------------- K3: finalize (vectorized) -----------------------------------
__global__ void finalize_kernel(float* __restrict__ out) {
    int i = blockIdx.x * blockDim.x + threadIdx.x;   // 4 cols per thread
    if (i >= NODES * OC / 4) return;
    int n  = i >> 4;
    int c4 = (i & 15) * 4;
    float2 dp = *(float2*)(g_denom + n * 2);
    float i0 = 1.0f / (dp.x + 1e-16f);
    float i1 = 1.0f / (dp.y + 1e-16f);
    float4 a0 = *(float4*)(g_agg + (size_t)n * HC + c4);
    float4 a1 = *(float4*)(g_agg + (size_t)n * HC + 64 + c4);
    float4 xs = *(float4*)(g_xs + (size_t)n * OC + c4);
    float4 v;
    v.x = 0.5f * (a0.x * i0 + a1.x * i1) + xs.x;
    v.y = 0.5f * (a0.y * i0 + a1.y * i1) + xs.y;
    v.z = 0.5f * (a0.z * i0 + a1.z * i1) + xs.z;
    v.w = 0.5f * (a0.w * i0 + a1.w * i1) + xs.w;
    *(float4*)(out + (size_t)n * OC + c4) = v;
}

// ---------------- launch ------------------------------------------------------
extern "C" void kernel_launch(void* const* d_in, const int* in_sizes, int n_in,
                              void* d_out, int out_size) {
    const float* x        = (const float*)d_in[0];
    const float* edge_attr= (const float*)d_in[1];
    const float* W_msg    = (const float*)d_in[2];
    const float* b_msg    = (const float*)d_in[3];
    const float* W_edge   = (const float*)d_in[4];
    const float* b_edge   = (const float*)d_in[5];
    const float* W_self   = (const float*)d_in[6];
    const float* b_self   = (const float*)d_in[7];
    const float* att      = (const float*)d_in[8];
    const int*   ei       = (const int*)d_in[9];
    const int* srcI = ei;
    const int* dstI = ei + EDGES;

    float* out = (float*)d_out;
    float* le_out;
    bool le_in_out = (out_size >= NODES * OC + (long long)EDGES * HC);
    if (le_in_out) {
        le_out = out + (size_t)NODES * OC;
    } else {
        void* p = nullptr;
        cudaGetSymbolAddress(&p, g_le_fallback);
        le_out = (float*)p;
    }

    cudaFuncSetAttribute(node_kernel, cudaFuncAttributeMaxDynamicSharedMemorySize, NSM_TOTAL);
    cudaFuncSetAttribute(edge_kernel, cudaFuncAttributeMaxDynamicSharedMemorySize, SM_TOTAL);

    setup_kernel<<<(NODES * HC / 4 + 255) / 256, 256>>>(W_edge, W_msg, W_self);
    node_kernel<<<NT_TILES, 384, NSM_TOTAL>>>(x, b_msg, b_self);
    edge_kernel<<<296, 256, SM_TOTAL>>>(edge_attr, b_edge, att, srcI, dstI, le_out);
    finalize_kernel<<<(NODES * OC / 4 + 255) / 256, 256>>>(out);
}